// round 1
// baseline (speedup 1.0000x reference)
#include <cuda_runtime.h>

#define CC 128            // channels
#define KK_TAPS 27
#define TM 128            // rows per tile
#define XS_STRIDE 132     // padded strides (float4-aligned, reduces LDS conflicts)
#define WS_STRIDE 132
#define NEG_SLOPE 0.2f

#define N_MAX 200000
// scratch: conv1 accumulator and conv2 output, each [N, C]
__device__ float g_tmp1[(size_t)N_MAX * CC];
__device__ float g_tmp2[(size_t)N_MAX * CC];

static const int SMEM_BYTES = (CC * WS_STRIDE + TM * XS_STRIDE) * (int)sizeof(float);

__device__ __forceinline__ float lrelu(float x) {
    return x >= 0.0f ? x : NEG_SLOPE * x;
}

// ---------------------------------------------------------------------------
// Sparse conv tap: dst[out_map[k,m]] += feats[in_map[k,m]] @ W[k]
// One CTA: tap k (blockIdx.y), rows [blockIdx.x*TM, +TM) of m.
// ---------------------------------------------------------------------------
__global__ __launch_bounds__(256, 1)
void sparse_conv_atomic(const float* __restrict__ src,
                        const float* __restrict__ W,
                        const int* __restrict__ in_map,
                        const int* __restrict__ out_map,
                        float* __restrict__ dst,
                        int Mtot)
{
    extern __shared__ float sm[];
    float* Ws = sm;                         // [CC][WS_STRIDE], Ws[cin][cout]
    float* Xs = sm + CC * WS_STRIDE;        // [TM][XS_STRIDE]

    const int k    = blockIdx.y;
    const float* Wk = W + (size_t)k * CC * CC;
    const int* im  = in_map  + (size_t)k * Mtot;
    const int* om  = out_map + (size_t)k * Mtot;
    const int row0 = blockIdx.x * TM;
    const int nrows = min(TM, Mtot - row0);
    const int tid  = threadIdx.x;

    // Load W[k] (128x128 fp32) into smem, coalesced float4.
    #pragma unroll
    for (int it = 0; it < 16; ++it) {
        int idx = tid + it * 256;           // 0..4095 float4s
        int r = idx >> 5, c4 = idx & 31;
        float4 v = ((const float4*)(Wk + (size_t)r * CC))[c4];
        *(float4*)(Ws + r * WS_STRIDE + c4 * 4) = v;
    }
    // Gather X rows via in_map (zero-fill tail of partial tiles).
    #pragma unroll
    for (int it = 0; it < 16; ++it) {
        int idx = tid + it * 256;
        int r = idx >> 5, c4 = idx & 31;
        float4 v = make_float4(0.f, 0.f, 0.f, 0.f);
        if (r < nrows) {
            int srow = im[row0 + r];
            v = ((const float4*)(src + (size_t)srow * CC))[c4];
        }
        *(float4*)(Xs + r * XS_STRIDE + c4 * 4) = v;
    }
    __syncthreads();

    const int tx = tid & 7;    // col group: cols [tx*16, +16)
    const int ty = tid >> 3;   // row group: rows [ty*4, +4)

    float acc[4][16];
    #pragma unroll
    for (int i = 0; i < 4; ++i)
        #pragma unroll
        for (int j = 0; j < 16; ++j) acc[i][j] = 0.0f;

    const float* xb = Xs + (ty * 4) * XS_STRIDE;
    const float* wb = Ws + tx * 16;

    #pragma unroll 2
    for (int kk = 0; kk < CC; ++kk) {
        float xv[4];
        #pragma unroll
        for (int i = 0; i < 4; ++i) xv[i] = xb[i * XS_STRIDE + kk];
        #pragma unroll
        for (int j4 = 0; j4 < 4; ++j4) {
            float4 w = *(const float4*)(wb + kk * WS_STRIDE + j4 * 4);
            #pragma unroll
            for (int i = 0; i < 4; ++i) {
                acc[i][j4 * 4 + 0] += xv[i] * w.x;
                acc[i][j4 * 4 + 1] += xv[i] * w.y;
                acc[i][j4 * 4 + 2] += xv[i] * w.z;
                acc[i][j4 * 4 + 3] += xv[i] * w.w;
            }
        }
    }

    // Scatter-add (REDG.32, no return).
    #pragma unroll
    for (int i = 0; i < 4; ++i) {
        int r = ty * 4 + i;
        if (r < nrows) {
            int drow = om[row0 + r];
            float* d = dst + (size_t)drow * CC + tx * 16;
            #pragma unroll
            for (int j = 0; j < 16; ++j) atomicAdd(d + j, acc[i][j]);
        }
    }
}

// ---------------------------------------------------------------------------
// Dense layer: dst = lrelu( lrelu(src) @ W2 ).  (conv1 epilogue fused on load)
// ---------------------------------------------------------------------------
__global__ __launch_bounds__(256, 1)
void dense_lrelu(const float* __restrict__ src,
                 const float* __restrict__ W,
                 float* __restrict__ dst,
                 int Ntot)
{
    extern __shared__ float sm[];
    float* Ws = sm;
    float* Xs = sm + CC * WS_STRIDE;

    const int row0 = blockIdx.x * TM;
    const int nrows = min(TM, Ntot - row0);
    const int tid = threadIdx.x;

    #pragma unroll
    for (int it = 0; it < 16; ++it) {
        int idx = tid + it * 256;
        int r = idx >> 5, c4 = idx & 31;
        float4 v = ((const float4*)(W + (size_t)r * CC))[c4];
        *(float4*)(Ws + r * WS_STRIDE + c4 * 4) = v;
    }
    #pragma unroll
    for (int it = 0; it < 16; ++it) {
        int idx = tid + it * 256;
        int r = idx >> 5, c4 = idx & 31;
        float4 v = make_float4(0.f, 0.f, 0.f, 0.f);
        if (r < nrows) {
            v = ((const float4*)(src + (size_t)(row0 + r) * CC))[c4];
            v.x = lrelu(v.x); v.y = lrelu(v.y); v.z = lrelu(v.z); v.w = lrelu(v.w);
        }
        *(float4*)(Xs + r * XS_STRIDE + c4 * 4) = v;
    }
    __syncthreads();

    const int tx = tid & 7;
    const int ty = tid >> 3;

    float acc[4][16];
    #pragma unroll
    for (int i = 0; i < 4; ++i)
        #pragma unroll
        for (int j = 0; j < 16; ++j) acc[i][j] = 0.0f;

    const float* xb = Xs + (ty * 4) * XS_STRIDE;
    const float* wb = Ws + tx * 16;

    #pragma unroll 2
    for (int kk = 0; kk < CC; ++kk) {
        float xv[4];
        #pragma unroll
        for (int i = 0; i < 4; ++i) xv[i] = xb[i * XS_STRIDE + kk];
        #pragma unroll
        for (int j4 = 0; j4 < 4; ++j4) {
            float4 w = *(const float4*)(wb + kk * WS_STRIDE + j4 * 4);
            #pragma unroll
            for (int i = 0; i < 4; ++i) {
                acc[i][j4 * 4 + 0] += xv[i] * w.x;
                acc[i][j4 * 4 + 1] += xv[i] * w.y;
                acc[i][j4 * 4 + 2] += xv[i] * w.z;
                acc[i][j4 * 4 + 3] += xv[i] * w.w;
            }
        }
    }

    #pragma unroll
    for (int i = 0; i < 4; ++i) {
        int r = ty * 4 + i;
        if (r < nrows) {
            float* d = dst + (size_t)(row0 + r) * CC + tx * 16;
            #pragma unroll
            for (int j4 = 0; j4 < 4; ++j4) {
                float4 v;
                v.x = lrelu(acc[i][j4 * 4 + 0]);
                v.y = lrelu(acc[i][j4 * 4 + 1]);
                v.z = lrelu(acc[i][j4 * 4 + 2]);
                v.w = lrelu(acc[i][j4 * 4 + 3]);
                *(float4*)(d + j4 * 4) = v;
            }
        }
    }
}

// ---------------------------------------------------------------------------
// Utility kernels
// ---------------------------------------------------------------------------
__global__ void zero2_kernel(float* __restrict__ a, float* __restrict__ b, int n4)
{
    int i = blockIdx.x * blockDim.x + threadIdx.x;
    float4 z = make_float4(0.f, 0.f, 0.f, 0.f);
    if (i < n4) {
        ((float4*)a)[i] = z;
        ((float4*)b)[i] = z;
    }
}

__global__ void mask_scale_kernel(float* __restrict__ out,
                                  const float* __restrict__ mask, int n4)
{
    int i = blockIdx.x * blockDim.x + threadIdx.x;
    if (i < n4) {
        float m = mask[i >> 5];        // 32 float4s per 128-col row
        float4 v = ((float4*)out)[i];
        v.x *= m; v.y *= m; v.z *= m; v.w *= m;
        ((float4*)out)[i] = v;
    }
}

// ---------------------------------------------------------------------------
// Launch
// ---------------------------------------------------------------------------
extern "C" void kernel_launch(void* const* d_in, const int* in_sizes, int n_in,
                              void* d_out, int out_size)
{
    const float* feats   = (const float*)d_in[0];
    const float* W1      = (const float*)d_in[1];
    const float* W2      = (const float*)d_in[2];
    const float* W3      = (const float*)d_in[3];
    const int*   in_map  = (const int*)d_in[4];
    const int*   out_map = (const int*)d_in[5];
    const float* mask    = (const float*)d_in[6];
    float* out = (float*)d_out;

    const int Ntot = in_sizes[0] / CC;        // 200000
    const int Mtot = in_sizes[4] / KK_TAPS;   // 100000

    cudaFuncSetAttribute(sparse_conv_atomic,
                         cudaFuncAttributeMaxDynamicSharedMemorySize, SMEM_BYTES);
    cudaFuncSetAttribute(dense_lrelu,
                         cudaFuncAttributeMaxDynamicSharedMemorySize, SMEM_BYTES);

    float* tmp1 = nullptr;
    float* tmp2 = nullptr;
    cudaGetSymbolAddress((void**)&tmp1, g_tmp1);
    cudaGetSymbolAddress((void**)&tmp2, g_tmp2);

    const int n4 = Ntot * CC / 4;

    // 1) zero conv1 accumulator and d_out (conv3 accumulator)
    zero2_kernel<<<(n4 + 255) / 256, 256>>>(tmp1, out, n4);

    // 2) conv1: feats -> tmp1 (pre-activation accumulate)
    {
        dim3 grid((Mtot + TM - 1) / TM, KK_TAPS);
        sparse_conv_atomic<<<grid, 256, SMEM_BYTES>>>(feats, W1, in_map, out_map,
                                                      tmp1, Mtot);
    }

    // 3) c2 = lrelu( lrelu(tmp1) @ W2 ) -> tmp2
    {
        dim3 grid((Ntot + TM - 1) / TM);
        dense_lrelu<<<grid, 256, SMEM_BYTES>>>(tmp1, W2, tmp2, Ntot);
    }

    // 4) conv3: tmp2 -> d_out (accumulate)
    {
        dim3 grid((Mtot + TM - 1) / TM, KK_TAPS);
        sparse_conv_atomic<<<grid, 256, SMEM_BYTES>>>(tmp2, W3, in_map, out_map,
                                                      out, Mtot);
    }

    // 5) out *= mask (row-broadcast)
    mask_scale_kernel<<<(n4 + 255) / 256, 256>>>(out, mask, n4);
}

// round 2
// speedup vs baseline: 1.0019x; 1.0019x over previous
#include <cuda_runtime.h>

#define CC 128            // channels
#define KK_TAPS 27
#define TM 128            // rows per tile
#define XS_STRIDE 132     // padded strides (float4-aligned, reduces LDS conflicts)
#define WS_STRIDE 132
#define NEG_SLOPE 0.2f

#define N_MAX 200000
// scratch: conv1 accumulator and conv2 output, each [N, C]
__device__ float g_tmp1[(size_t)N_MAX * CC];
__device__ float g_tmp2[(size_t)N_MAX * CC];

static const int SMEM_BYTES = (CC * WS_STRIDE + TM * XS_STRIDE) * (int)sizeof(float);

__device__ __forceinline__ float lrelu(float x) {
    return x >= 0.0f ? x : NEG_SLOPE * x;
}

// ---------------------------------------------------------------------------
// Sparse conv tap: dst[out_map[k,m]] += feats[in_map[k,m]] @ W[k]
// One CTA: tap k (blockIdx.y), rows [blockIdx.x*TM, +TM) of m.
// ---------------------------------------------------------------------------
__global__ __launch_bounds__(256, 1)
void sparse_conv_atomic(const float* __restrict__ src,
                        const float* __restrict__ W,
                        const int* __restrict__ in_map,
                        const int* __restrict__ out_map,
                        float* __restrict__ dst,
                        int Mtot)
{
    extern __shared__ float sm[];
    float* Ws = sm;                         // [CC][WS_STRIDE], Ws[cin][cout]
    float* Xs = sm + CC * WS_STRIDE;        // [TM][XS_STRIDE]

    const int k    = blockIdx.y;
    const float* Wk = W + (size_t)k * CC * CC;
    const int* im  = in_map  + (size_t)k * Mtot;
    const int* om  = out_map + (size_t)k * Mtot;
    const int row0 = blockIdx.x * TM;
    const int nrows = min(TM, Mtot - row0);
    const int tid  = threadIdx.x;

    // Load W[k] (128x128 fp32) into smem, coalesced float4.
    #pragma unroll
    for (int it = 0; it < 16; ++it) {
        int idx = tid + it * 256;           // 0..4095 float4s
        int r = idx >> 5, c4 = idx & 31;
        float4 v = ((const float4*)(Wk + (size_t)r * CC))[c4];
        *(float4*)(Ws + r * WS_STRIDE + c4 * 4) = v;
    }
    // Gather X rows via in_map (zero-fill tail of partial tiles).
    #pragma unroll
    for (int it = 0; it < 16; ++it) {
        int idx = tid + it * 256;
        int r = idx >> 5, c4 = idx & 31;
        float4 v = make_float4(0.f, 0.f, 0.f, 0.f);
        if (r < nrows) {
            int srow = im[row0 + r];
            v = ((const float4*)(src + (size_t)srow * CC))[c4];
        }
        *(float4*)(Xs + r * XS_STRIDE + c4 * 4) = v;
    }
    __syncthreads();

    const int tx = tid & 7;    // col group: cols [tx*16, +16)
    const int ty = tid >> 3;   // row group: rows [ty*4, +4)

    float acc[4][16];
    #pragma unroll
    for (int i = 0; i < 4; ++i)
        #pragma unroll
        for (int j = 0; j < 16; ++j) acc[i][j] = 0.0f;

    const float* xb = Xs + (ty * 4) * XS_STRIDE;
    const float* wb = Ws + tx * 16;

    #pragma unroll 2
    for (int kk = 0; kk < CC; ++kk) {
        float xv[4];
        #pragma unroll
        for (int i = 0; i < 4; ++i) xv[i] = xb[i * XS_STRIDE + kk];
        #pragma unroll
        for (int j4 = 0; j4 < 4; ++j4) {
            float4 w = *(const float4*)(wb + kk * WS_STRIDE + j4 * 4);
            #pragma unroll
            for (int i = 0; i < 4; ++i) {
                acc[i][j4 * 4 + 0] += xv[i] * w.x;
                acc[i][j4 * 4 + 1] += xv[i] * w.y;
                acc[i][j4 * 4 + 2] += xv[i] * w.z;
                acc[i][j4 * 4 + 3] += xv[i] * w.w;
            }
        }
    }

    // Scatter-add (REDG.32, no return).
    #pragma unroll
    for (int i = 0; i < 4; ++i) {
        int r = ty * 4 + i;
        if (r < nrows) {
            int drow = om[row0 + r];
            float* d = dst + (size_t)drow * CC + tx * 16;
            #pragma unroll
            for (int j = 0; j < 16; ++j) atomicAdd(d + j, acc[i][j]);
        }
    }
}

// ---------------------------------------------------------------------------
// Dense layer: dst = lrelu( lrelu(src) @ W2 ).  (conv1 epilogue fused on load)
// ---------------------------------------------------------------------------
__global__ __launch_bounds__(256, 1)
void dense_lrelu(const float* __restrict__ src,
                 const float* __restrict__ W,
                 float* __restrict__ dst,
                 int Ntot)
{
    extern __shared__ float sm[];
    float* Ws = sm;
    float* Xs = sm + CC * WS_STRIDE;

    const int row0 = blockIdx.x * TM;
    const int nrows = min(TM, Ntot - row0);
    const int tid = threadIdx.x;

    #pragma unroll
    for (int it = 0; it < 16; ++it) {
        int idx = tid + it * 256;
        int r = idx >> 5, c4 = idx & 31;
        float4 v = ((const float4*)(W + (size_t)r * CC))[c4];
        *(float4*)(Ws + r * WS_STRIDE + c4 * 4) = v;
    }
    #pragma unroll
    for (int it = 0; it < 16; ++it) {
        int idx = tid + it * 256;
        int r = idx >> 5, c4 = idx & 31;
        float4 v = make_float4(0.f, 0.f, 0.f, 0.f);
        if (r < nrows) {
            v = ((const float4*)(src + (size_t)(row0 + r) * CC))[c4];
            v.x = lrelu(v.x); v.y = lrelu(v.y); v.z = lrelu(v.z); v.w = lrelu(v.w);
        }
        *(float4*)(Xs + r * XS_STRIDE + c4 * 4) = v;
    }
    __syncthreads();

    const int tx = tid & 7;
    const int ty = tid >> 3;

    float acc[4][16];
    #pragma unroll
    for (int i = 0; i < 4; ++i)
        #pragma unroll
        for (int j = 0; j < 16; ++j) acc[i][j] = 0.0f;

    const float* xb = Xs + (ty * 4) * XS_STRIDE;
    const float* wb = Ws + tx * 16;

    #pragma unroll 2
    for (int kk = 0; kk < CC; ++kk) {
        float xv[4];
        #pragma unroll
        for (int i = 0; i < 4; ++i) xv[i] = xb[i * XS_STRIDE + kk];
        #pragma unroll
        for (int j4 = 0; j4 < 4; ++j4) {
            float4 w = *(const float4*)(wb + kk * WS_STRIDE + j4 * 4);
            #pragma unroll
            for (int i = 0; i < 4; ++i) {
                acc[i][j4 * 4 + 0] += xv[i] * w.x;
                acc[i][j4 * 4 + 1] += xv[i] * w.y;
                acc[i][j4 * 4 + 2] += xv[i] * w.z;
                acc[i][j4 * 4 + 3] += xv[i] * w.w;
            }
        }
    }

    #pragma unroll
    for (int i = 0; i < 4; ++i) {
        int r = ty * 4 + i;
        if (r < nrows) {
            float* d = dst + (size_t)(row0 + r) * CC + tx * 16;
            #pragma unroll
            for (int j4 = 0; j4 < 4; ++j4) {
                float4 v;
                v.x = lrelu(acc[i][j4 * 4 + 0]);
                v.y = lrelu(acc[i][j4 * 4 + 1]);
                v.z = lrelu(acc[i][j4 * 4 + 2]);
                v.w = lrelu(acc[i][j4 * 4 + 3]);
                *(float4*)(d + j4 * 4) = v;
            }
        }
    }
}

// ---------------------------------------------------------------------------
// Utility kernels
// ---------------------------------------------------------------------------
__global__ void zero2_kernel(float* __restrict__ a, float* __restrict__ b, int n4)
{
    int i = blockIdx.x * blockDim.x + threadIdx.x;
    float4 z = make_float4(0.f, 0.f, 0.f, 0.f);
    if (i < n4) {
        ((float4*)a)[i] = z;
        ((float4*)b)[i] = z;
    }
}

__global__ void mask_scale_kernel(float* __restrict__ out,
                                  const float* __restrict__ mask, int n4)
{
    int i = blockIdx.x * blockDim.x + threadIdx.x;
    if (i < n4) {
        float m = mask[i >> 5];        // 32 float4s per 128-col row
        float4 v = ((float4*)out)[i];
        v.x *= m; v.y *= m; v.z *= m; v.w *= m;
        ((float4*)out)[i] = v;
    }
}

// ---------------------------------------------------------------------------
// Launch
// ---------------------------------------------------------------------------
extern "C" void kernel_launch(void* const* d_in, const int* in_sizes, int n_in,
                              void* d_out, int out_size)
{
    const float* feats   = (const float*)d_in[0];
    const float* W1      = (const float*)d_in[1];
    const float* W2      = (const float*)d_in[2];
    const float* W3      = (const float*)d_in[3];
    const int*   in_map  = (const int*)d_in[4];
    const int*   out_map = (const int*)d_in[5];
    const float* mask    = (const float*)d_in[6];
    float* out = (float*)d_out;

    const int Ntot = in_sizes[0] / CC;        // 200000
    const int Mtot = in_sizes[4] / KK_TAPS;   // 100000

    cudaFuncSetAttribute(sparse_conv_atomic,
                         cudaFuncAttributeMaxDynamicSharedMemorySize, SMEM_BYTES);
    cudaFuncSetAttribute(dense_lrelu,
                         cudaFuncAttributeMaxDynamicSharedMemorySize, SMEM_BYTES);

    float* tmp1 = nullptr;
    float* tmp2 = nullptr;
    cudaGetSymbolAddress((void**)&tmp1, g_tmp1);
    cudaGetSymbolAddress((void**)&tmp2, g_tmp2);

    const int n4 = Ntot * CC / 4;

    // 1) zero conv1 accumulator and d_out (conv3 accumulator)
    zero2_kernel<<<(n4 + 255) / 256, 256>>>(tmp1, out, n4);

    // 2) conv1: feats -> tmp1 (pre-activation accumulate)
    {
        dim3 grid((Mtot + TM - 1) / TM, KK_TAPS);
        sparse_conv_atomic<<<grid, 256, SMEM_BYTES>>>(feats, W1, in_map, out_map,
                                                      tmp1, Mtot);
    }

    // 3) c2 = lrelu( lrelu(tmp1) @ W2 ) -> tmp2
    {
        dim3 grid((Ntot + TM - 1) / TM);
        dense_lrelu<<<grid, 256, SMEM_BYTES>>>(tmp1, W2, tmp2, Ntot);
    }

    // 4) conv3: tmp2 -> d_out (accumulate)
    {
        dim3 grid((Mtot + TM - 1) / TM, KK_TAPS);
        sparse_conv_atomic<<<grid, 256, SMEM_BYTES>>>(tmp2, W3, in_map, out_map,
                                                      out, Mtot);
    }

    // 5) out *= mask (row-broadcast)
    mask_scale_kernel<<<(n4 + 255) / 256, 256>>>(out, mask, n4);
}

// round 4
// speedup vs baseline: 4.8816x; 4.8723x over previous
#include <cuda_runtime.h>
#include <cuda_bf16.h>
#include <cstdint>

#define CC 128
#define KTAPS 27
#define NEG_SLOPE 0.2f
#define NMAX 200000
#define ASTRIDE 272          // bytes per smem A row (17 x 16B)

__device__ float g_tmp1[(size_t)NMAX * CC];
__device__ float g_tmp2[(size_t)NMAX * CC];
// B fragments in mma.m16n8k16 register layout: [tap][kchunk8][ntile16][lane32][2]
__device__ uint32_t g_f1h[KTAPS * 8192];
__device__ uint32_t g_f1l[KTAPS * 8192];
__device__ uint32_t g_f3h[KTAPS * 8192];
__device__ uint32_t g_f3l[KTAPS * 8192];
__device__ uint32_t g_f2h[8192];
__device__ uint32_t g_f2l[8192];

__device__ __forceinline__ uint32_t smem_u32(const void* p) {
    uint32_t a;
    asm("{ .reg .u64 t; cvta.to.shared.u64 t, %1; cvt.u32.u64 %0, t; }" : "=r"(a) : "l"(p));
    return a;
}
__device__ __forceinline__ float lrelu(float x) { return x >= 0.0f ? x : NEG_SLOPE * x; }
__device__ __forceinline__ void split2(float a, float b, uint32_t& hi, uint32_t& lo) {
    __nv_bfloat162 h = __floats2bfloat162_rn(a, b);
    __nv_bfloat162 l = __floats2bfloat162_rn(a - __bfloat162float(h.x), b - __bfloat162float(h.y));
    hi = *reinterpret_cast<uint32_t*>(&h);
    lo = *reinterpret_cast<uint32_t*>(&l);
}

#define LDSM4(r, addr) \
    asm volatile("ldmatrix.sync.aligned.m8n8.x4.shared.b16 {%0,%1,%2,%3}, [%4];" \
        : "=r"((r)[0]), "=r"((r)[1]), "=r"((r)[2]), "=r"((r)[3]) : "r"(addr))

#define MMA_BF16(c, a, b0, b1) \
    asm volatile("mma.sync.aligned.m16n8k16.row.col.f32.bf16.bf16.f32 " \
        "{%0,%1,%2,%3}, {%4,%5,%6,%7}, {%8,%9}, {%0,%1,%2,%3};" \
        : "+f"((c)[0]), "+f"((c)[1]), "+f"((c)[2]), "+f"((c)[3]) \
        : "r"((a)[0]), "r"((a)[1]), "r"((a)[2]), "r"((a)[3]), "r"(b0), "r"(b1))

// ---------------------------------------------------------------------------
// Weight fragment prep: W[tap][cin][cout] -> hi/lo bf16 fragments, mma layout.
// idx = ((tap*8 + kc)*16 + nt)*32 + lane ; regs (k0,k0+1) and (k0+8,k0+9), col n.
// ---------------------------------------------------------------------------
__global__ void wfrag(const float* __restrict__ W, uint32_t* __restrict__ fh,
                      uint32_t* __restrict__ fl, int taps)
{
    int idx = blockIdx.x * blockDim.x + threadIdx.x;
    if (idx >= taps * 4096) return;
    int lane = idx & 31, nt = (idx >> 5) & 15, kc = (idx >> 9) & 7, tap = idx >> 12;
    int n = nt * 8 + (lane >> 2);
    int k0 = kc * 16 + 2 * (lane & 3);
    const float* Wt = W + (size_t)tap * CC * CC;
    float x0 = Wt[(size_t)k0 * CC + n],       x1 = Wt[(size_t)(k0 + 1) * CC + n];
    float x2 = Wt[(size_t)(k0 + 8) * CC + n], x3 = Wt[(size_t)(k0 + 9) * CC + n];
    uint32_t h0, l0, h1, l1;
    split2(x0, x1, h0, l0);
    split2(x2, x3, h1, l1);
    fh[(size_t)idx * 2] = h0; fh[(size_t)idx * 2 + 1] = h1;
    fl[(size_t)idx * 2] = l0; fl[(size_t)idx * 2 + 1] = l1;
}

// ---------------------------------------------------------------------------
// Sparse conv tap tile: 64 gathered rows x 128 cols, bf16x3 HMMA, red scatter
// ---------------------------------------------------------------------------
__global__ __launch_bounds__(128, 3)
void conv_mma(const float* __restrict__ src,
              const uint32_t* __restrict__ fh, const uint32_t* __restrict__ fl,
              const int* __restrict__ in_map, const int* __restrict__ out_map,
              float* __restrict__ dst, int Mtot)
{
    extern __shared__ char dsm[];
    __shared__ int irow[64];
    const uint32_t AHI = smem_u32(dsm), ALO = AHI + 64 * ASTRIDE;
    const int tid = threadIdx.x, wid = tid >> 5, lane = tid & 31;
    const int tap = blockIdx.y;
    const int row0 = blockIdx.x * 64;
    const int nrows = min(64, Mtot - row0);

    if (tid < 64)
        irow[tid] = (tid < nrows) ? in_map[(size_t)tap * Mtot + row0 + tid] : -1;
    __syncthreads();

    // gather + split fill: 64 rows x 32 float4
    #pragma unroll
    for (int it = 0; it < 16; ++it) {
        int idx = tid + it * 128;
        int r = idx >> 5, c4 = idx & 31;
        int srow = irow[r];
        uint32_t h0 = 0, h1 = 0, l0 = 0, l1 = 0;
        if (srow >= 0) {
            float4 v = *reinterpret_cast<const float4*>(src + (size_t)srow * CC + c4 * 4);
            split2(v.x, v.y, h0, l0);
            split2(v.z, v.w, h1, l1);
        }
        uint32_t off = r * ASTRIDE + c4 * 8;
        asm volatile("st.shared.v2.b32 [%0], {%1,%2};" :: "r"(AHI + off), "r"(h0), "r"(h1) : "memory");
        asm volatile("st.shared.v2.b32 [%0], {%1,%2};" :: "r"(ALO + off), "r"(l0), "r"(l1) : "memory");
    }
    __syncthreads();

    float acc[64];
    #pragma unroll
    for (int i = 0; i < 64; ++i) acc[i] = 0.0f;

    const uint32_t* fhp = fh + (size_t)tap * 8192;
    const uint32_t* flp = fl + (size_t)tap * 8192;
    const int arow = wid * 16 + (lane & 15);
    const uint32_t abh = AHI + arow * ASTRIDE + (lane >> 4) * 16;
    const uint32_t abl = ALO + arow * ASTRIDE + (lane >> 4) * 16;

    #pragma unroll
    for (int kc = 0; kc < 8; ++kc) {
        uint32_t ah[4], al[4];
        LDSM4(ah, abh + kc * 32);
        LDSM4(al, abl + kc * 32);
        #pragma unroll
        for (int nt = 0; nt < 16; ++nt) {
            size_t f = ((size_t)(kc * 16 + nt) * 32 + lane) * 2;
            uint2 bh = *reinterpret_cast<const uint2*>(fhp + f);
            uint2 bl = *reinterpret_cast<const uint2*>(flp + f);
            MMA_BF16(acc + nt * 4, ah, bh.x, bh.y);
            MMA_BF16(acc + nt * 4, ah, bl.x, bl.y);
            MMA_BF16(acc + nt * 4, al, bh.x, bh.y);
        }
    }

    // scatter: lane holds rows (wid*16 + lane/4) and +8, cols nt*8 + 2*(lane&3)+{0,1}
    const int r0w = wid * 16 + (lane >> 2), r1w = r0w + 8;
    const int g0 = (r0w < nrows) ? out_map[(size_t)tap * Mtot + row0 + r0w] : -1;
    const int g1 = (r1w < nrows) ? out_map[(size_t)tap * Mtot + row0 + r1w] : -1;
    const int cb = (lane & 3) * 2;
    #pragma unroll
    for (int nt = 0; nt < 16; ++nt) {
        int col = nt * 8 + cb;
        if (g0 >= 0)
            asm volatile("red.global.add.v2.f32 [%0], {%1,%2};"
                :: "l"(dst + (size_t)g0 * CC + col), "f"(acc[nt*4+0]), "f"(acc[nt*4+1]) : "memory");
        if (g1 >= 0)
            asm volatile("red.global.add.v2.f32 [%0], {%1,%2};"
                :: "l"(dst + (size_t)g1 * CC + col), "f"(acc[nt*4+2]), "f"(acc[nt*4+3]) : "memory");
    }
}

// ---------------------------------------------------------------------------
// Dense: tmp2 = lrelu( lrelu(tmp1) @ W2 )
// ---------------------------------------------------------------------------
__global__ __launch_bounds__(128, 3)
void dense_mma(const float* __restrict__ src,
               const uint32_t* __restrict__ fh, const uint32_t* __restrict__ fl,
               float* __restrict__ dstp, int Ntot)
{
    extern __shared__ char dsm[];
    const uint32_t AHI = smem_u32(dsm), ALO = AHI + 64 * ASTRIDE;
    const int tid = threadIdx.x, wid = tid >> 5, lane = tid & 31;
    const int row0 = blockIdx.x * 64;
    const int nrows = min(64, Ntot - row0);

    #pragma unroll
    for (int it = 0; it < 16; ++it) {
        int idx = tid + it * 128;
        int r = idx >> 5, c4 = idx & 31;
        uint32_t h0 = 0, h1 = 0, l0 = 0, l1 = 0;
        if (r < nrows) {
            float4 v = *reinterpret_cast<const float4*>(src + (size_t)(row0 + r) * CC + c4 * 4);
            split2(lrelu(v.x), lrelu(v.y), h0, l0);
            split2(lrelu(v.z), lrelu(v.w), h1, l1);
        }
        uint32_t off = r * ASTRIDE + c4 * 8;
        asm volatile("st.shared.v2.b32 [%0], {%1,%2};" :: "r"(AHI + off), "r"(h0), "r"(h1) : "memory");
        asm volatile("st.shared.v2.b32 [%0], {%1,%2};" :: "r"(ALO + off), "r"(l0), "r"(l1) : "memory");
    }
    __syncthreads();

    float acc[64];
    #pragma unroll
    for (int i = 0; i < 64; ++i) acc[i] = 0.0f;

    const int arow = wid * 16 + (lane & 15);
    const uint32_t abh = AHI + arow * ASTRIDE + (lane >> 4) * 16;
    const uint32_t abl = ALO + arow * ASTRIDE + (lane >> 4) * 16;

    #pragma unroll
    for (int kc = 0; kc < 8; ++kc) {
        uint32_t ah[4], al[4];
        LDSM4(ah, abh + kc * 32);
        LDSM4(al, abl + kc * 32);
        #pragma unroll
        for (int nt = 0; nt < 16; ++nt) {
            size_t f = ((size_t)(kc * 16 + nt) * 32 + lane) * 2;
            uint2 bh = *reinterpret_cast<const uint2*>(fh + f);
            uint2 bl = *reinterpret_cast<const uint2*>(fl + f);
            MMA_BF16(acc + nt * 4, ah, bh.x, bh.y);
            MMA_BF16(acc + nt * 4, ah, bl.x, bl.y);
            MMA_BF16(acc + nt * 4, al, bh.x, bh.y);
        }
    }

    const int r0w = wid * 16 + (lane >> 2), r1w = r0w + 8;
    const int cb = (lane & 3) * 2;
    #pragma unroll
    for (int nt = 0; nt < 16; ++nt) {
        int col = nt * 8 + cb;
        if (r0w < nrows) {
            float2 v = make_float2(lrelu(acc[nt*4+0]), lrelu(acc[nt*4+1]));
            *reinterpret_cast<float2*>(dstp + (size_t)(row0 + r0w) * CC + col) = v;
        }
        if (r1w < nrows) {
            float2 v = make_float2(lrelu(acc[nt*4+2]), lrelu(acc[nt*4+3]));
            *reinterpret_cast<float2*>(dstp + (size_t)(row0 + r1w) * CC + col) = v;
        }
    }
}

// ---------------------------------------------------------------------------
__global__ void zero2_kernel(float* __restrict__ a, float* __restrict__ b, int n4)
{
    int i = blockIdx.x * blockDim.x + threadIdx.x;
    float4 z = make_float4(0.f, 0.f, 0.f, 0.f);
    if (i < n4) { ((float4*)a)[i] = z; ((float4*)b)[i] = z; }
}
__global__ void mask_scale_kernel(float* __restrict__ out, const float* __restrict__ mask, int n4)
{
    int i = blockIdx.x * blockDim.x + threadIdx.x;
    if (i < n4) {
        float m = mask[i >> 5];
        float4 v = ((float4*)out)[i];
        v.x *= m; v.y *= m; v.z *= m; v.w *= m;
        ((float4*)out)[i] = v;
    }
}

extern "C" void kernel_launch(void* const* d_in, const int* in_sizes, int n_in,
                              void* d_out, int out_size)
{
    const float* feats   = (const float*)d_in[0];
    const float* W1      = (const float*)d_in[1];
    const float* W2      = (const float*)d_in[2];
    const float* W3      = (const float*)d_in[3];
    const int*   in_map  = (const int*)d_in[4];
    const int*   out_map = (const int*)d_in[5];
    const float* mask    = (const float*)d_in[6];
    float* out = (float*)d_out;

    const int Ntot = in_sizes[0] / CC;
    const int Mtot = in_sizes[4] / KTAPS;
    const int SMEM = 64 * ASTRIDE * 2;   // 34816 B

    float *tmp1, *tmp2;
    uint32_t *f1h, *f1l, *f3h, *f3l, *f2h, *f2l;
    cudaGetSymbolAddress((void**)&tmp1, g_tmp1);
    cudaGetSymbolAddress((void**)&tmp2, g_tmp2);
    cudaGetSymbolAddress((void**)&f1h, g_f1h);
    cudaGetSymbolAddress((void**)&f1l, g_f1l);
    cudaGetSymbolAddress((void**)&f3h, g_f3h);
    cudaGetSymbolAddress((void**)&f3l, g_f3l);
    cudaGetSymbolAddress((void**)&f2h, g_f2h);
    cudaGetSymbolAddress((void**)&f2l, g_f2l);

    const int n4 = Ntot * CC / 4;

    zero2_kernel<<<(n4 + 255) / 256, 256>>>(tmp1, out, n4);
    wfrag<<<(KTAPS * 4096 + 255) / 256, 256>>>(W1, f1h, f1l, KTAPS);
    wfrag<<<(KTAPS * 4096 + 255) / 256, 256>>>(W3, f3h, f3l, KTAPS);
    wfrag<<<16, 256>>>(W2, f2h, f2l, 1);

    dim3 cgrid((Mtot + 63) / 64, KTAPS);
    conv_mma<<<cgrid, 128, SMEM>>>(feats, f1h, f1l, in_map, out_map, tmp1, Mtot);
    dense_mma<<<(Ntot + 63) / 64, 128, SMEM>>>(tmp1, f2h, f2l, tmp2, Ntot);
    conv_mma<<<cgrid, 128, SMEM>>>(tmp2, f3h, f3l, in_map, out_map, out, Mtot);
    mask_scale_kernel<<<(n4 + 255) / 256, 256>>>(out, mask, n4);
}

// round 5
// speedup vs baseline: 5.4220x; 1.1107x over previous
#include <cuda_runtime.h>
#include <cuda_fp16.h>
#include <cstdint>

#define CC 128
#define KTAPS 27
#define NEG_SLOPE 0.2f
#define NMAX 200000
#define ASTRIDE 272          // bytes per smem A row (17 x 16B)

__device__ float g_tmp1[(size_t)NMAX * CC];
__device__ float g_tmp2[(size_t)NMAX * CC];
// B fragments (single fp16) in mma.m16n8k16 layout: [tap][kc8][nt16][lane32][2]
__device__ uint32_t g_f1[KTAPS * 8192];
__device__ uint32_t g_f3[KTAPS * 8192];
__device__ uint32_t g_f2[8192];

__device__ __forceinline__ uint32_t smem_u32(const void* p) {
    uint32_t a;
    asm("{ .reg .u64 t; cvta.to.shared.u64 t, %1; cvt.u32.u64 %0, t; }" : "=r"(a) : "l"(p));
    return a;
}
__device__ __forceinline__ float lrelu(float x) { return x >= 0.0f ? x : NEG_SLOPE * x; }

// fp16 split: x = hi + lo
__device__ __forceinline__ void split2(float a, float b, uint32_t& hi, uint32_t& lo) {
    __half2 h = __floats2half2_rn(a, b);
    __half2 l = __floats2half2_rn(a - __half2float(h.x), b - __half2float(h.y));
    hi = *reinterpret_cast<uint32_t*>(&h);
    lo = *reinterpret_cast<uint32_t*>(&l);
}

#define LDSM4(r, addr) \
    asm volatile("ldmatrix.sync.aligned.m8n8.x4.shared.b16 {%0,%1,%2,%3}, [%4];" \
        : "=r"((r)[0]), "=r"((r)[1]), "=r"((r)[2]), "=r"((r)[3]) : "r"(addr))

#define MMA_F16(c, a, b0, b1) \
    asm volatile("mma.sync.aligned.m16n8k16.row.col.f32.f16.f16.f32 " \
        "{%0,%1,%2,%3}, {%4,%5,%6,%7}, {%8,%9}, {%0,%1,%2,%3};" \
        : "+f"((c)[0]), "+f"((c)[1]), "+f"((c)[2]), "+f"((c)[3]) \
        : "r"((a)[0]), "r"((a)[1]), "r"((a)[2]), "r"((a)[3]), "r"(b0), "r"(b1))

// ---------------------------------------------------------------------------
// Weight fragment prep: W[tap][cin][cout] -> fp16 fragments, mma B layout.
// ---------------------------------------------------------------------------
__global__ void wfrag(const float* __restrict__ W, uint32_t* __restrict__ fB, int taps)
{
    int idx = blockIdx.x * blockDim.x + threadIdx.x;
    if (idx >= taps * 4096) return;
    int lane = idx & 31, nt = (idx >> 5) & 15, kc = (idx >> 9) & 7, tap = idx >> 12;
    int n = nt * 8 + (lane >> 2);
    int k0 = kc * 16 + 2 * (lane & 3);
    const float* Wt = W + (size_t)tap * CC * CC;
    __half2 b0 = __floats2half2_rn(Wt[(size_t)k0 * CC + n],       Wt[(size_t)(k0 + 1) * CC + n]);
    __half2 b1 = __floats2half2_rn(Wt[(size_t)(k0 + 8) * CC + n], Wt[(size_t)(k0 + 9) * CC + n]);
    fB[(size_t)idx * 2]     = *reinterpret_cast<uint32_t*>(&b0);
    fB[(size_t)idx * 2 + 1] = *reinterpret_cast<uint32_t*>(&b1);
}

// ---------------------------------------------------------------------------
// Sparse conv tap tile: 64 gathered rows x 128 cols, fp16x2 HMMA, red scatter
// ---------------------------------------------------------------------------
__global__ __launch_bounds__(128, 3)
void conv_mma(const float* __restrict__ src,
              const uint32_t* __restrict__ fB,
              const int* __restrict__ in_map, const int* __restrict__ out_map,
              float* __restrict__ dst, int Mtot)
{
    extern __shared__ char dsm[];
    __shared__ int irow[64];
    const uint32_t AHI = smem_u32(dsm), ALO = AHI + 64 * ASTRIDE;
    const int tid = threadIdx.x, wid = tid >> 5, lane = tid & 31;
    const int tap = blockIdx.y;
    const int row0 = blockIdx.x * 64;
    const int nrows = min(64, Mtot - row0);

    if (tid < 64)
        irow[tid] = (tid < nrows) ? in_map[(size_t)tap * Mtot + row0 + tid] : -1;
    __syncthreads();

    #pragma unroll
    for (int it = 0; it < 16; ++it) {
        int idx = tid + it * 128;
        int r = idx >> 5, c4 = idx & 31;
        int srow = irow[r];
        uint32_t h0 = 0, h1 = 0, l0 = 0, l1 = 0;
        if (srow >= 0) {
            float4 v = *reinterpret_cast<const float4*>(src + (size_t)srow * CC + c4 * 4);
            split2(v.x, v.y, h0, l0);
            split2(v.z, v.w, h1, l1);
        }
        uint32_t off = r * ASTRIDE + c4 * 8;
        asm volatile("st.shared.v2.b32 [%0], {%1,%2};" :: "r"(AHI + off), "r"(h0), "r"(h1) : "memory");
        asm volatile("st.shared.v2.b32 [%0], {%1,%2};" :: "r"(ALO + off), "r"(l0), "r"(l1) : "memory");
    }
    __syncthreads();

    float acc[64];
    #pragma unroll
    for (int i = 0; i < 64; ++i) acc[i] = 0.0f;

    const uint32_t* fp = fB + (size_t)tap * 8192;
    const int arow = wid * 16 + (lane & 15);
    const uint32_t abh = AHI + arow * ASTRIDE + (lane >> 4) * 16;
    const uint32_t abl = ALO + arow * ASTRIDE + (lane >> 4) * 16;

    #pragma unroll
    for (int kc = 0; kc < 8; ++kc) {
        uint32_t ah[4], al[4];
        LDSM4(ah, abh + kc * 32);
        LDSM4(al, abl + kc * 32);
        #pragma unroll
        for (int nt = 0; nt < 16; ++nt) {
            uint2 b = *reinterpret_cast<const uint2*>(fp + ((size_t)(kc * 16 + nt) * 32 + lane) * 2);
            MMA_F16(acc + nt * 4, ah, b.x, b.y);
            MMA_F16(acc + nt * 4, al, b.x, b.y);
        }
    }

    const int r0w = wid * 16 + (lane >> 2), r1w = r0w + 8;
    const int g0 = (r0w < nrows) ? out_map[(size_t)tap * Mtot + row0 + r0w] : -1;
    const int g1 = (r1w < nrows) ? out_map[(size_t)tap * Mtot + row0 + r1w] : -1;
    const int cb = (lane & 3) * 2;
    #pragma unroll
    for (int nt = 0; nt < 16; ++nt) {
        int col = nt * 8 + cb;
        if (g0 >= 0)
            asm volatile("red.global.add.v2.f32 [%0], {%1,%2};"
                :: "l"(dst + (size_t)g0 * CC + col), "f"(acc[nt*4+0]), "f"(acc[nt*4+1]) : "memory");
        if (g1 >= 0)
            asm volatile("red.global.add.v2.f32 [%0], {%1,%2};"
                :: "l"(dst + (size_t)g1 * CC + col), "f"(acc[nt*4+2]), "f"(acc[nt*4+3]) : "memory");
    }
}

// ---------------------------------------------------------------------------
// Dense: tmp2 = lrelu( lrelu(tmp1) @ W2 )
// ---------------------------------------------------------------------------
__global__ __launch_bounds__(128, 3)
void dense_mma(const float* __restrict__ src,
               const uint32_t* __restrict__ fB,
               float* __restrict__ dstp, int Ntot)
{
    extern __shared__ char dsm[];
    const uint32_t AHI = smem_u32(dsm), ALO = AHI + 64 * ASTRIDE;
    const int tid = threadIdx.x, wid = tid >> 5, lane = tid & 31;
    const int row0 = blockIdx.x * 64;
    const int nrows = min(64, Ntot - row0);

    #pragma unroll
    for (int it = 0; it < 16; ++it) {
        int idx = tid + it * 128;
        int r = idx >> 5, c4 = idx & 31;
        uint32_t h0 = 0, h1 = 0, l0 = 0, l1 = 0;
        if (r < nrows) {
            float4 v = *reinterpret_cast<const float4*>(src + (size_t)(row0 + r) * CC + c4 * 4);
            split2(lrelu(v.x), lrelu(v.y), h0, l0);
            split2(lrelu(v.z), lrelu(v.w), h1, l1);
        }
        uint32_t off = r * ASTRIDE + c4 * 8;
        asm volatile("st.shared.v2.b32 [%0], {%1,%2};" :: "r"(AHI + off), "r"(h0), "r"(h1) : "memory");
        asm volatile("st.shared.v2.b32 [%0], {%1,%2};" :: "r"(ALO + off), "r"(l0), "r"(l1) : "memory");
    }
    __syncthreads();

    float acc[64];
    #pragma unroll
    for (int i = 0; i < 64; ++i) acc[i] = 0.0f;

    const int arow = wid * 16 + (lane & 15);
    const uint32_t abh = AHI + arow * ASTRIDE + (lane >> 4) * 16;
    const uint32_t abl = ALO + arow * ASTRIDE + (lane >> 4) * 16;

    #pragma unroll
    for (int kc = 0; kc < 8; ++kc) {
        uint32_t ah[4], al[4];
        LDSM4(ah, abh + kc * 32);
        LDSM4(al, abl + kc * 32);
        #pragma unroll
        for (int nt = 0; nt < 16; ++nt) {
            uint2 b = *reinterpret_cast<const uint2*>(fB + ((size_t)(kc * 16 + nt) * 32 + lane) * 2);
            MMA_F16(acc + nt * 4, ah, b.x, b.y);
            MMA_F16(acc + nt * 4, al, b.x, b.y);
        }
    }

    const int r0w = wid * 16 + (lane >> 2), r1w = r0w + 8;
    const int cb = (lane & 3) * 2;
    #pragma unroll
    for (int nt = 0; nt < 16; ++nt) {
        int col = nt * 8 + cb;
        if (r0w < nrows) {
            float2 v = make_float2(lrelu(acc[nt*4+0]), lrelu(acc[nt*4+1]));
            *reinterpret_cast<float2*>(dstp + (size_t)(row0 + r0w) * CC + col) = v;
        }
        if (r1w < nrows) {
            float2 v = make_float2(lrelu(acc[nt*4+2]), lrelu(acc[nt*4+3]));
            *reinterpret_cast<float2*>(dstp + (size_t)(row0 + r1w) * CC + col) = v;
        }
    }
}

// ---------------------------------------------------------------------------
__global__ void zero2_kernel(float* __restrict__ a, float* __restrict__ b, int n4)
{
    int i = blockIdx.x * blockDim.x + threadIdx.x;
    float4 z = make_float4(0.f, 0.f, 0.f, 0.f);
    if (i < n4) { ((float4*)a)[i] = z; ((float4*)b)[i] = z; }
}
__global__ void mask_scale_kernel(float* __restrict__ out, const float* __restrict__ mask, int n4)
{
    int i = blockIdx.x * blockDim.x + threadIdx.x;
    if (i < n4) {
        float m = mask[i >> 5];
        float4 v = ((float4*)out)[i];
        v.x *= m; v.y *= m; v.z *= m; v.w *= m;
        ((float4*)out)[i] = v;
    }
}

extern "C" void kernel_launch(void* const* d_in, const int* in_sizes, int n_in,
                              void* d_out, int out_size)
{
    const float* feats   = (const float*)d_in[0];
    const float* W1      = (const float*)d_in[1];
    const float* W2      = (const float*)d_in[2];
    const float* W3      = (const float*)d_in[3];
    const int*   in_map  = (const int*)d_in[4];
    const int*   out_map = (const int*)d_in[5];
    const float* mask    = (const float*)d_in[6];
    float* out = (float*)d_out;

    const int Ntot = in_sizes[0] / CC;
    const int Mtot = in_sizes[4] / KTAPS;
    const int SMEM = 64 * ASTRIDE * 2;   // 34816 B

    float *tmp1, *tmp2;
    uint32_t *f1, *f3, *f2;
    cudaGetSymbolAddress((void**)&tmp1, g_tmp1);
    cudaGetSymbolAddress((void**)&tmp2, g_tmp2);
    cudaGetSymbolAddress((void**)&f1, g_f1);
    cudaGetSymbolAddress((void**)&f3, g_f3);
    cudaGetSymbolAddress((void**)&f2, g_f2);

    const int n4 = Ntot * CC / 4;

    zero2_kernel<<<(n4 + 255) / 256, 256>>>(tmp1, out, n4);
    wfrag<<<(KTAPS * 4096 + 255) / 256, 256>>>(W1, f1, KTAPS);
    wfrag<<<(KTAPS * 4096 + 255) / 256, 256>>>(W3, f3, KTAPS);
    wfrag<<<16, 256>>>(W2, f2, 1);

    dim3 cgrid((Mtot + 63) / 64, KTAPS);
    conv_mma<<<cgrid, 128, SMEM>>>(feats, f1, in_map, out_map, tmp1, Mtot);
    dense_mma<<<(Ntot + 63) / 64, 128, SMEM>>>(tmp1, f2, tmp2, Ntot);
    conv_mma<<<cgrid, 128, SMEM>>>(tmp2, f3, in_map, out_map, out, Mtot);
    mask_scale_kernel<<<(n4 + 255) / 256, 256>>>(out, mask, n4);
}